// round 1
// baseline (speedup 1.0000x reference)
#include <cuda_runtime.h>
#include <cstdint>

#define NNODES 100000
#define MHE    200000
#define NEDGE  2000000
#define INF_   16
#define HIDF   64

typedef unsigned long long ull;

// ---------------- scratch (static __device__ — no allocations allowed) ----------------
static __device__ __align__(16) float4 g_she[2 * MHE * 4];      // [t][he][16] as float4[4]
static __device__ __align__(16) float4 g_agg[2 * NNODES * 4];   // [t][n][16]  as float4[4]
static __device__ __align__(16) float  g_bdeg[2 * MHE];         // counts -> inverted in place
static __device__ __align__(16) float  g_ddeg[2 * NNODES];      // counts -> inverted in place
static __device__ __align__(16) float  g_H[NNODES * HIDF];      // relu(mix) output
static __device__ __align__(16) float  g_Wcm[2 * INF_ * HIDF];  // W_conv[t] @ W_mix_t  [t][i][j]
static __device__ __align__(16) float  g_bprime[HIDF];
// GRU weights, pre-transposed to [k][j] layout for coalesced smem fill
static __device__ __align__(16) float  g_Wr[128 * 64];
static __device__ __align__(16) float  g_Wz[128 * 64];
static __device__ __align__(16) float  g_Wni[64 * 64];
static __device__ __align__(16) float  g_Wnh[64 * 64];
static __device__ __align__(16) float  g_br[64], g_bz[64], g_bni[64], g_bnh[64];

// ---------------- helpers ----------------
__device__ __forceinline__ void red4(float4* addr, float4 v) {
    asm volatile("red.global.add.v4.f32 [%0], {%1,%2,%3,%4};"
                 :: "l"(addr), "f"(v.x), "f"(v.y), "f"(v.z), "f"(v.w) : "memory");
}
__device__ __forceinline__ void red1(float* addr, float v) {
    asm volatile("red.global.add.f32 [%0], %1;" :: "l"(addr), "f"(v) : "memory");
}
__device__ __forceinline__ ull pk2(float lo, float hi) {
    ull r; asm("mov.b64 %0,{%1,%2};" : "=l"(r) : "f"(lo), "f"(hi)); return r;
}
__device__ __forceinline__ float2 up2(ull v) {
    float2 r; asm("mov.b64 {%0,%1},%2;" : "=f"(r.x), "=f"(r.y) : "l"(v)); return r;
}
__device__ __forceinline__ ull f2fma(ull a, ull b, ull c) {
    ull d; asm("fma.rn.f32x2 %0,%1,%2,%3;" : "=l"(d) : "l"(a), "l"(b), "l"(c)); return d;
}
__device__ __forceinline__ float sigf(float x) { return 1.f / (1.f + expf(-x)); }

// ---------------- kernels ----------------

// zero all accumulation scratch (2.55M float4)
__global__ void k_zero() {
    int i = blockIdx.x * 256 + threadIdx.x;
    float4 z = make_float4(0.f, 0.f, 0.f, 0.f);
    if (i < 1600000) g_she[i] = z;
    int j = i - 1600000; if (j >= 0 && j < 800000) g_agg[j] = z;
    int k = i - 2400000; if (k >= 0 && k < 100000) ((float4*)g_bdeg)[k] = z;
    int l = i - 2500000; if (l >= 0 && l < 50000)  ((float4*)g_ddeg)[l] = z;
}

// precompute Wcm[t][i][j] = sum_k W_conv[t][i][k] * W_mix[t*64+k][j], and b'
__global__ void k_prew(const float* __restrict__ Wc, const float* __restrict__ bc,
                       const float* __restrict__ Wm, const float* __restrict__ bm) {
    int idx = blockIdx.x * 256 + threadIdx.x;
    if (idx < 2048) {
        int t = idx >> 10, rem = idx & 1023, i = rem >> 6, j = rem & 63;
        float acc = 0.f;
        for (int k = 0; k < 64; k++)
            acc += Wc[(t * 16 + i) * 64 + k] * Wm[(t * 64 + k) * 64 + j];
        g_Wcm[idx] = acc;
    } else if (idx < 2112) {
        int j = idx - 2048;
        float acc = bm[j];
        for (int t = 0; t < 2; t++)
            for (int k = 0; k < 64; k++)
                acc += bc[t * 64 + k] * Wm[(t * 64 + k) * 64 + j];
        g_bprime[j] = acc;
    }
}

// pre-transpose GRU weights into [k][j] layout; combine biases
__global__ void k_pregru(const float* __restrict__ Wih, const float* __restrict__ Whh,
                         const float* __restrict__ bih, const float* __restrict__ bhh) {
    int idx = blockIdx.x * 256 + threadIdx.x;   // < 8192
    int k = idx >> 6, j = idx & 63;
    g_Wr[idx] = (k < 64) ? Wih[j * 64 + k]          : Whh[j * 64 + (k - 64)];
    g_Wz[idx] = (k < 64) ? Wih[(64 + j) * 64 + k]   : Whh[(64 + j) * 64 + (k - 64)];
    if (k < 64) {  // idx < 4096
        g_Wni[idx] = Wih[(128 + j) * 64 + k];
        g_Wnh[idx] = Whh[(128 + j) * 64 + k];
    }
    if (idx < 64) {
        g_br[idx]  = bih[idx] + bhh[idx];
        g_bz[idx]  = bih[64 + idx] + bhh[64 + idx];
        g_bni[idx] = bih[128 + idx];
        g_bnh[idx] = bhh[128 + idx];
    }
}

// phase A: s_he[t][he] += x[node]; degree counts. 4 lanes per edge.
__global__ void k_scat1(const int* __restrict__ en, const int* __restrict__ eh,
                        const int* __restrict__ ea, const float4* __restrict__ x4) {
    int gid = blockIdx.x * 256 + threadIdx.x;
    int e = gid >> 2;
    if (e >= NEDGE) return;
    int sub = gid & 3;
    int node = __ldg(en + e), he = __ldg(eh + e), t = __ldg(ea + e);
    float4 v = x4[node * 4 + sub];
    red4(&g_she[(t * MHE + he) * 4 + sub], v);
    if (sub == 0) {
        red1(&g_bdeg[t * MHE + he], 1.f);
        red1(&g_ddeg[t * NNODES + node], 1.f);
    }
}

// invert degrees in place
__global__ void k_inv() {
    int i = blockIdx.x * 256 + threadIdx.x;
    if (i < 2 * MHE) {
        float v = g_bdeg[i];
        g_bdeg[i] = (v > 0.f) ? 1.f / v : 0.f;
    } else {
        int j = i - 2 * MHE;
        if (j < 2 * NNODES) {
            float v = g_ddeg[j];
            g_ddeg[j] = (v > 0.f) ? 1.f / v : 0.f;
        }
    }
}

// phase B: agg_n[t][node] += Binv[t][he] * s_he[t][he]. 4 lanes per edge.
__global__ void k_scat2(const int* __restrict__ en, const int* __restrict__ eh,
                        const int* __restrict__ ea) {
    int gid = blockIdx.x * 256 + threadIdx.x;
    int e = gid >> 2;
    if (e >= NEDGE) return;
    int sub = gid & 3;
    int node = __ldg(en + e), he = __ldg(eh + e), t = __ldg(ea + e);
    float bi = g_bdeg[t * MHE + he];   // already inverted
    float4 v = g_she[(t * MHE + he) * 4 + sub];
    v.x *= bi; v.y *= bi; v.z *= bi; v.w *= bi;
    red4(&g_agg[(t * NNODES + node) * 4 + sub], v);
}

// H[n] = relu( sum_t (Dinv_t[n]*agg_t[n]) @ Wcm[t] + b' )
__global__ __launch_bounds__(256) void k_mix(int Nn) {
    __shared__ float wcm[2048];
    __shared__ float bp[64];
    int tid = threadIdx.x;
    for (int i = tid; i < 2048; i += 256) wcm[i] = g_Wcm[i];
    if (tid < 64) bp[tid] = g_bprime[tid];
    __syncthreads();
    int n = blockIdx.x * 256 + tid;
    if (n >= Nn) return;
    float a[32];
    float d0 = g_ddeg[n], d1 = g_ddeg[NNODES + n];
    const float4* A0 = &g_agg[n * 4];
    const float4* A1 = &g_agg[(NNODES + n) * 4];
#pragma unroll
    for (int q = 0; q < 4; q++) {
        float4 v = A0[q];
        a[q * 4 + 0] = v.x * d0; a[q * 4 + 1] = v.y * d0;
        a[q * 4 + 2] = v.z * d0; a[q * 4 + 3] = v.w * d0;
    }
#pragma unroll
    for (int q = 0; q < 4; q++) {
        float4 v = A1[q];
        a[16 + q * 4 + 0] = v.x * d1; a[16 + q * 4 + 1] = v.y * d1;
        a[16 + q * 4 + 2] = v.z * d1; a[16 + q * 4 + 3] = v.w * d1;
    }
    const float4* w4 = (const float4*)wcm;
    const float4* b4 = (const float4*)bp;
    for (int jb = 0; jb < 16; jb++) {
        float4 acc = b4[jb];
#pragma unroll
        for (int i = 0; i < 16; i++) {
            float4 w = w4[i * 16 + jb];           // t=0
            acc.x += a[i] * w.x; acc.y += a[i] * w.y;
            acc.z += a[i] * w.z; acc.w += a[i] * w.w;
            float4 w2 = w4[(16 + i) * 16 + jb];   // t=1
            acc.x += a[16 + i] * w2.x; acc.y += a[16 + i] * w2.y;
            acc.z += a[16 + i] * w2.z; acc.w += a[16 + i] * w2.w;
        }
        acc.x = fmaxf(acc.x, 0.f); acc.y = fmaxf(acc.y, 0.f);
        acc.z = fmaxf(acc.z, 0.f); acc.w = fmaxf(acc.w, 0.f);
        ((float4*)g_H)[n * 16 + jb] = acc;
    }
}

// fused GRU: h_next = (1-z)*tanh(i_n + r*h_n) + z*h_prev, written straight to d_out.
// Tile: 128 nodes/block, 256 threads, each thread = 4 nodes x 8 gate-outputs (f32x2 packed).
#define XP 132
__global__ __launch_bounds__(256, 1) void k_gru(const float* __restrict__ hprev,
                                                float* __restrict__ out, int Nn) {
    extern __shared__ float sm[];
    float* Xs  = sm;                  // [128][XP]: k<64 = H, k>=64 = h_prev
    float* Wr  = sm + 128 * XP;       // [128][64]
    float* Wz  = Wr + 8192;
    float* Wni = Wz + 8192;           // [64][64]
    float* Wnh = Wni + 4096;
    float* br  = Wnh + 4096;
    float* bz  = br + 64;
    float* bni = bz + 64;
    float* bnh = bni + 64;
    const int tid = threadIdx.x;

    for (int i = tid; i < 2048; i += 256) {
        ((float4*)Wr)[i] = ((const float4*)g_Wr)[i];
        ((float4*)Wz)[i] = ((const float4*)g_Wz)[i];
    }
    for (int i = tid; i < 1024; i += 256) {
        ((float4*)Wni)[i] = ((const float4*)g_Wni)[i];
        ((float4*)Wnh)[i] = ((const float4*)g_Wnh)[i];
    }
    if (tid < 64) { br[tid] = g_br[tid]; bz[tid] = g_bz[tid];
                    bni[tid] = g_bni[tid]; bnh[tid] = g_bnh[tid]; }

    int nbase = blockIdx.x * 128;
    for (int fl = tid; fl < 128 * 32; fl += 256) {
        int n = fl >> 5, q = fl & 31;
        int gn = nbase + n;
        float4 v = make_float4(0.f, 0.f, 0.f, 0.f);
        if (gn < Nn)
            v = (q < 16) ? ((const float4*)g_H)[gn * 16 + q]
                         : ((const float4*)hprev)[gn * 16 + (q - 16)];
        *(float4*)&Xs[n * XP + q * 4] = v;
    }
    __syncthreads();

    const int ng = tid >> 3;          // 0..31 node-group
    const int jg = tid & 7;           // 0..7  gate-group
    const int j0 = jg * 8;
    const float* Xb = &Xs[(ng * 4) * XP];

    ull ar[16], az[16];
#pragma unroll
    for (int jj = 0; jj < 4; jj++) {
        ull b_r = pk2(br[j0 + 2 * jj], br[j0 + 2 * jj + 1]);
        ull b_z = pk2(bz[j0 + 2 * jj], bz[j0 + 2 * jj + 1]);
#pragma unroll
        for (int n = 0; n < 4; n++) { ar[n * 4 + jj] = b_r; az[n * 4 + jj] = b_z; }
    }
    // pass 1: r,z over concat [H ; h_prev]  (k = 0..127)
#pragma unroll 2
    for (int k = 0; k < 128; k++) {
        float x0 = Xb[k], x1 = Xb[XP + k], x2 = Xb[2 * XP + k], x3 = Xb[3 * XP + k];
        ull xx[4] = { pk2(x0, x0), pk2(x1, x1), pk2(x2, x2), pk2(x3, x3) };
        ulonglong2 wra = *(const ulonglong2*)&Wr[k * 64 + j0];
        ulonglong2 wrb = *(const ulonglong2*)&Wr[k * 64 + j0 + 4];
        ulonglong2 wza = *(const ulonglong2*)&Wz[k * 64 + j0];
        ulonglong2 wzb = *(const ulonglong2*)&Wz[k * 64 + j0 + 4];
#pragma unroll
        for (int n = 0; n < 4; n++) {
            ar[n * 4 + 0] = f2fma(xx[n], wra.x, ar[n * 4 + 0]);
            ar[n * 4 + 1] = f2fma(xx[n], wra.y, ar[n * 4 + 1]);
            ar[n * 4 + 2] = f2fma(xx[n], wrb.x, ar[n * 4 + 2]);
            ar[n * 4 + 3] = f2fma(xx[n], wrb.y, ar[n * 4 + 3]);
            az[n * 4 + 0] = f2fma(xx[n], wza.x, az[n * 4 + 0]);
            az[n * 4 + 1] = f2fma(xx[n], wza.y, az[n * 4 + 1]);
            az[n * 4 + 2] = f2fma(xx[n], wzb.x, az[n * 4 + 2]);
            az[n * 4 + 3] = f2fma(xx[n], wzb.y, az[n * 4 + 3]);
        }
    }
    // pass 2: i_n over H, h_n over h_prev  (k = 0..63)
    ull ani[16], anh[16];
#pragma unroll
    for (int jj = 0; jj < 4; jj++) {
        ull b_i = pk2(bni[j0 + 2 * jj], bni[j0 + 2 * jj + 1]);
        ull b_h = pk2(bnh[j0 + 2 * jj], bnh[j0 + 2 * jj + 1]);
#pragma unroll
        for (int n = 0; n < 4; n++) { ani[n * 4 + jj] = b_i; anh[n * 4 + jj] = b_h; }
    }
#pragma unroll 2
    for (int k = 0; k < 64; k++) {
        float h0 = Xb[k], h1 = Xb[XP + k], h2 = Xb[2 * XP + k], h3 = Xb[3 * XP + k];
        float p0 = Xb[64 + k], p1 = Xb[XP + 64 + k], p2 = Xb[2 * XP + 64 + k], p3 = Xb[3 * XP + 64 + k];
        ull xh[4] = { pk2(h0, h0), pk2(h1, h1), pk2(h2, h2), pk2(h3, h3) };
        ull xp[4] = { pk2(p0, p0), pk2(p1, p1), pk2(p2, p2), pk2(p3, p3) };
        ulonglong2 wia = *(const ulonglong2*)&Wni[k * 64 + j0];
        ulonglong2 wib = *(const ulonglong2*)&Wni[k * 64 + j0 + 4];
        ulonglong2 wha = *(const ulonglong2*)&Wnh[k * 64 + j0];
        ulonglong2 whb = *(const ulonglong2*)&Wnh[k * 64 + j0 + 4];
#pragma unroll
        for (int n = 0; n < 4; n++) {
            ani[n * 4 + 0] = f2fma(xh[n], wia.x, ani[n * 4 + 0]);
            ani[n * 4 + 1] = f2fma(xh[n], wia.y, ani[n * 4 + 1]);
            ani[n * 4 + 2] = f2fma(xh[n], wib.x, ani[n * 4 + 2]);
            ani[n * 4 + 3] = f2fma(xh[n], wib.y, ani[n * 4 + 3]);
            anh[n * 4 + 0] = f2fma(xp[n], wha.x, anh[n * 4 + 0]);
            anh[n * 4 + 1] = f2fma(xp[n], wha.y, anh[n * 4 + 1]);
            anh[n * 4 + 2] = f2fma(xp[n], whb.x, anh[n * 4 + 2]);
            anh[n * 4 + 3] = f2fma(xp[n], whb.y, anh[n * 4 + 3]);
        }
    }
    // combine + store h_next
#pragma unroll
    for (int n = 0; n < 4; n++) {
        int gn = nbase + ng * 4 + n;
        if (gn >= Nn) continue;
        float res[8];
#pragma unroll
        for (int jj = 0; jj < 4; jj++) {
            float2 rr = up2(ar[n * 4 + jj]);
            float2 zz = up2(az[n * 4 + jj]);
            float2 vi = up2(ani[n * 4 + jj]);
            float2 vh = up2(anh[n * 4 + jj]);
#pragma unroll
            for (int s = 0; s < 2; s++) {
                float r = sigf(s ? rr.y : rr.x);
                float z = sigf(s ? zz.y : zz.x);
                float nn = tanhf((s ? vi.y : vi.x) + r * (s ? vh.y : vh.x));
                float hp = Xb[n * XP + 64 + j0 + jj * 2 + s];
                res[jj * 2 + s] = (1.f - z) * nn + z * hp;
            }
        }
        float4* o = (float4*)&out[gn * 64 + j0];
        o[0] = make_float4(res[0], res[1], res[2], res[3]);
        o[1] = make_float4(res[4], res[5], res[6], res[7]);
    }
}

// pred_xyz = (h_next @ W_out + b_out)[:, :3]
__global__ __launch_bounds__(256) void k_pred(const float* __restrict__ Wout,
                                              const float* __restrict__ bout,
                                              float* __restrict__ out, int Nn) {
    __shared__ float wo[192];
    int tid = threadIdx.x;
    if (tid < 192) { int j = tid / 3, c = tid % 3; wo[tid] = Wout[j * 64 + c]; }
    __syncthreads();
    int n = blockIdx.x * 256 + tid;
    if (n >= Nn) return;
    const float* h = out + (size_t)n * 64;
    float a0 = bout[0], a1 = bout[1], a2 = bout[2];
#pragma unroll
    for (int j = 0; j < 64; j++) {
        float hv = h[j];
        a0 += hv * wo[j * 3 + 0];
        a1 += hv * wo[j * 3 + 1];
        a2 += hv * wo[j * 3 + 2];
    }
    float* p = out + (size_t)Nn * 64 + (size_t)n * 3;
    p[0] = a0; p[1] = a1; p[2] = a2;
}

// ---------------- launch ----------------
extern "C" void kernel_launch(void* const* d_in, const int* in_sizes, int n_in,
                              void* d_out, int out_size) {
    const float* x     = (const float*)d_in[0];
    const float* hprev = (const float*)d_in[1];
    const int*   en    = (const int*)d_in[2];
    const int*   eh    = (const int*)d_in[3];
    const int*   ea    = (const int*)d_in[4];
    const float* Wconv = (const float*)d_in[5];
    const float* bconv = (const float*)d_in[6];
    const float* Wmix  = (const float*)d_in[7];
    const float* bmix  = (const float*)d_in[8];
    const float* Wih   = (const float*)d_in[9];
    const float* Whh   = (const float*)d_in[10];
    const float* bih   = (const float*)d_in[11];
    const float* bhh   = (const float*)d_in[12];
    const float* Wout  = (const float*)d_in[13];
    const float* bout  = (const float*)d_in[14];
    float* out = (float*)d_out;

    (void)in_sizes; (void)n_in; (void)out_size;

    k_zero<<<9961, 256>>>();
    k_prew<<<9, 256>>>(Wconv, bconv, Wmix, bmix);
    k_pregru<<<32, 256>>>(Wih, Whh, bih, bhh);
    k_scat1<<<31250, 256>>>(en, eh, ea, (const float4*)x);
    k_inv<<<2344, 256>>>();
    k_scat2<<<31250, 256>>>(en, eh, ea);
    k_mix<<<391, 256>>>(NNODES);

    const int smem = (128 * XP + 8192 * 2 + 4096 * 2 + 256) * 4;  // 166912 B
    cudaFuncSetAttribute(k_gru, cudaFuncAttributeMaxDynamicSharedMemorySize, smem);
    k_gru<<<782, 256, smem>>>(hprev, out, NNODES);

    k_pred<<<391, 256>>>(Wout, bout, out, NNODES);
}

// round 2
// speedup vs baseline: 1.0499x; 1.0499x over previous
#include <cuda_runtime.h>
#include <cstdint>

#define NNODES 100000
#define MHE    200000
#define NEDGE  2000000
#define INF_   16
#define HIDF   64
#define XP 132

typedef unsigned long long ull;

// ---------------- scratch (static __device__) ----------------
static __device__ __align__(16) float4 g_she[2 * MHE * 4];      // [t][he][16] as float4[4]
static __device__ __align__(16) float4 g_agg[2 * NNODES * 4];   // [t][n][16]  as float4[4]
static __device__ __align__(16) float  g_bdeg[2 * MHE];         // counts
static __device__ __align__(16) float  g_ddeg[2 * NNODES];      // counts
static __device__ __align__(16) float  g_Wcm[2 * INF_ * HIDF];  // W_conv[t] @ W_mix_t
static __device__ __align__(16) float  g_bprime[HIDF];
static __device__ __align__(16) float  g_Wr[128 * 64];
static __device__ __align__(16) float  g_Wz[128 * 64];
static __device__ __align__(16) float  g_Wni[64 * 64];
static __device__ __align__(16) float  g_Wnh[64 * 64];
static __device__ __align__(16) float  g_br[64], g_bz[64], g_bni[64], g_bnh[64];

// ---------------- helpers ----------------
__device__ __forceinline__ void red4(float4* addr, float4 v) {
    asm volatile("red.global.add.v4.f32 [%0], {%1,%2,%3,%4};"
                 :: "l"(addr), "f"(v.x), "f"(v.y), "f"(v.z), "f"(v.w) : "memory");
}
__device__ __forceinline__ void red1(float* addr, float v) {
    asm volatile("red.global.add.f32 [%0], %1;" :: "l"(addr), "f"(v) : "memory");
}
__device__ __forceinline__ ull pk2(float lo, float hi) {
    ull r; asm("mov.b64 %0,{%1,%2};" : "=l"(r) : "f"(lo), "f"(hi)); return r;
}
__device__ __forceinline__ float2 up2(ull v) {
    float2 r; asm("mov.b64 {%0,%1},%2;" : "=f"(r.x), "=f"(r.y) : "l"(v)); return r;
}
__device__ __forceinline__ ull f2fma(ull a, ull b, ull c) {
    ull d; asm("fma.rn.f32x2 %0,%1,%2,%3;" : "=l"(d) : "l"(a), "l"(b), "l"(c)); return d;
}
__device__ __forceinline__ float sigf(float x) { return 1.f / (1.f + expf(-x)); }

// ---------------- kernel 1: zero scratch + precompute weights ----------------
__global__ void k_pre(const float* __restrict__ Wc, const float* __restrict__ bc,
                      const float* __restrict__ Wm, const float* __restrict__ bm,
                      const float* __restrict__ Wih, const float* __restrict__ Whh,
                      const float* __restrict__ bih, const float* __restrict__ bhh) {
    int i = blockIdx.x * 256 + threadIdx.x;
    float4 z = make_float4(0.f, 0.f, 0.f, 0.f);
    if (i < 1600000) { g_she[i] = z; return; }
    int j = i - 1600000;
    if (j < 800000) { g_agg[j] = z; return; }
    int k = i - 2400000;
    if (k >= 0 && k < 100000) { ((float4*)g_bdeg)[k] = z; return; }
    int l = i - 2500000;
    if (l >= 0 && l < 50000) { ((float4*)g_ddeg)[l] = z; return; }
    int m = i - 2550000;
    if (m >= 0 && m < 2112) {
        if (m < 2048) {
            int t = m >> 10, rem = m & 1023, ii = rem >> 6, jj = rem & 63;
            float acc = 0.f;
            for (int kk = 0; kk < 64; kk++)
                acc += Wc[(t * 16 + ii) * 64 + kk] * Wm[(t * 64 + kk) * 64 + jj];
            g_Wcm[m] = acc;
        } else {
            int jj = m - 2048;
            float acc = bm[jj];
            for (int t = 0; t < 2; t++)
                for (int kk = 0; kk < 64; kk++)
                    acc += bc[t * 64 + kk] * Wm[(t * 64 + kk) * 64 + jj];
            g_bprime[jj] = acc;
        }
        return;
    }
    int p = i - 2552112;
    if (p >= 0 && p < 8192) {
        int kk = p >> 6, jj = p & 63;
        g_Wr[p] = (kk < 64) ? Wih[jj * 64 + kk]        : Whh[jj * 64 + (kk - 64)];
        g_Wz[p] = (kk < 64) ? Wih[(64 + jj) * 64 + kk] : Whh[(64 + jj) * 64 + (kk - 64)];
        if (kk < 64) {
            g_Wni[p] = Wih[(128 + jj) * 64 + kk];
            g_Wnh[p] = Whh[(128 + jj) * 64 + kk];
        }
        if (p < 64) {
            g_br[p]  = bih[p] + bhh[p];
            g_bz[p]  = bih[64 + p] + bhh[64 + p];
            g_bni[p] = bih[128 + p];
            g_bnh[p] = bhh[128 + p];
        }
    }
}

// ---------------- kernel 2: scatter x -> hyperedges + degree counts ----------------
__global__ void k_scat1(const int* __restrict__ en, const int* __restrict__ eh,
                        const int* __restrict__ ea, const float4* __restrict__ x4) {
    int gid = blockIdx.x * 256 + threadIdx.x;
    int e = gid >> 2;
    if (e >= NEDGE) return;
    int sub = gid & 3;
    int node = __ldg(en + e), he = __ldg(eh + e), t = __ldg(ea + e);
    float4 v = x4[node * 4 + sub];
    red4(&g_she[(t * MHE + he) * 4 + sub], v);
    if (sub == 0) red1(&g_bdeg[t * MHE + he], 1.f);
    else if (sub == 1) red1(&g_ddeg[t * NNODES + node], 1.f);
}

// ---------------- kernel 3: hyperedges -> nodes (Binv on the fly) ----------------
__global__ void k_scat2(const int* __restrict__ en, const int* __restrict__ eh,
                        const int* __restrict__ ea) {
    int gid = blockIdx.x * 256 + threadIdx.x;
    int e = gid >> 2;
    if (e >= NEDGE) return;
    int sub = gid & 3;
    int node = __ldg(en + e), he = __ldg(eh + e), t = __ldg(ea + e);
    float c = __ldg(&g_bdeg[t * MHE + he]);   // >= 1 for this edge's own key
    float bi = 1.0f / c;
    float4 v = g_she[(t * MHE + he) * 4 + sub];
    v.x *= bi; v.y *= bi; v.z *= bi; v.w *= bi;
    red4(&g_agg[(t * NNODES + node) * 4 + sub], v);
}

// ---------------- kernel 4: fused mix + GRU + pred ----------------
// 128 nodes/block, 256 threads; per-thread tile = 4 nodes x 8 gate-outputs.
__global__ __launch_bounds__(256, 1) void k_gru(const float* __restrict__ hprev,
                                                const float* __restrict__ Wout,
                                                const float* __restrict__ bout,
                                                float* __restrict__ out, int Nn) {
    extern __shared__ float sm[];
    float* Xs  = sm;                  // [128][XP]: cols 0..63 = H, 64..127 = h_prev
    float* Wr  = sm + 128 * XP;
    float* Wz  = Wr + 8192;
    float* Wni = Wz + 8192;
    float* Wnh = Wni + 4096;
    float* Wcm = Wnh + 4096;          // 2048
    float* br  = Wcm + 2048;
    float* bz  = br + 64;
    float* bni = bz + 64;
    float* bnh = bni + 64;
    float* bp  = bnh + 64;            // 64
    float* wo  = bp + 64;             // 192 (W_out transposed, [j*3+c])
    const int tid = threadIdx.x;

    for (int i = tid; i < 2048; i += 256) {
        ((float4*)Wr)[i] = ((const float4*)g_Wr)[i];
        ((float4*)Wz)[i] = ((const float4*)g_Wz)[i];
    }
    for (int i = tid; i < 1024; i += 256) {
        ((float4*)Wni)[i] = ((const float4*)g_Wni)[i];
        ((float4*)Wnh)[i] = ((const float4*)g_Wnh)[i];
    }
    for (int i = tid; i < 512; i += 256) ((float4*)Wcm)[i] = ((const float4*)g_Wcm)[i];
    if (tid < 64) { br[tid] = g_br[tid]; bz[tid] = g_bz[tid];
                    bni[tid] = g_bni[tid]; bnh[tid] = g_bnh[tid]; bp[tid] = g_bprime[tid]; }
    if (tid < 192) { int j = tid / 3, c = tid % 3; wo[tid] = Wout[j * 64 + c]; }

    const int nbase = blockIdx.x * 128;
    // stage h_prev into Xs cols 64..127
    for (int fl = tid; fl < 128 * 16; fl += 256) {
        int n = fl >> 4, q = fl & 15;
        int gn = nbase + n;
        float4 v = make_float4(0.f, 0.f, 0.f, 0.f);
        if (gn < Nn) v = ((const float4*)hprev)[gn * 16 + q];
        *(float4*)&Xs[n * XP + 64 + q * 4] = v;
    }

    const int ng = tid >> 3;          // 0..31
    const int jg = tid & 7;           // 0..7
    const int j0 = jg * 8;

    // ---- mix: H[row][j0..j0+7] for this thread's 4 nodes ----
    for (int n = 0; n < 4; n++) {
        int row = ng * 4 + n;
        int gn = nbase + row;
        float a[32];
        if (gn < Nn) {
            float c0 = __ldg(&g_ddeg[gn]), c1 = __ldg(&g_ddeg[NNODES + gn]);
            float d0 = (c0 > 0.f) ? 1.f / c0 : 0.f;
            float d1 = (c1 > 0.f) ? 1.f / c1 : 0.f;
#pragma unroll
            for (int q = 0; q < 4; q++) {
                float4 v = g_agg[(size_t)gn * 4 + q];
                a[q * 4 + 0] = v.x * d0; a[q * 4 + 1] = v.y * d0;
                a[q * 4 + 2] = v.z * d0; a[q * 4 + 3] = v.w * d0;
                float4 w = g_agg[(size_t)(NNODES + gn) * 4 + q];
                a[16 + q * 4 + 0] = w.x * d1; a[16 + q * 4 + 1] = w.y * d1;
                a[16 + q * 4 + 2] = w.z * d1; a[16 + q * 4 + 3] = w.w * d1;
            }
        } else {
#pragma unroll
            for (int q = 0; q < 32; q++) a[q] = 0.f;
        }
        float acc[8];
#pragma unroll
        for (int s = 0; s < 8; s++) acc[s] = bp[j0 + s];
#pragma unroll
        for (int i = 0; i < 16; i++) {
            float a0 = a[i], a1 = a[16 + i];
            const float* w0 = &Wcm[i * 64 + j0];
            const float* w1 = &Wcm[1024 + i * 64 + j0];
#pragma unroll
            for (int s = 0; s < 8; s++) acc[s] += a0 * w0[s] + a1 * w1[s];
        }
#pragma unroll
        for (int s = 0; s < 8; s++) acc[s] = fmaxf(acc[s], 0.f);
        *(float4*)&Xs[row * XP + j0]     = make_float4(acc[0], acc[1], acc[2], acc[3]);
        *(float4*)&Xs[row * XP + j0 + 4] = make_float4(acc[4], acc[5], acc[6], acc[7]);
    }
    __syncthreads();

    const float* Xb = &Xs[(ng * 4) * XP];

    // ---- pass 1: r,z over concat [H ; h_prev] ----
    ull ar[16], az[16];
#pragma unroll
    for (int jj = 0; jj < 4; jj++) {
        ull b_r = pk2(br[j0 + 2 * jj], br[j0 + 2 * jj + 1]);
        ull b_z = pk2(bz[j0 + 2 * jj], bz[j0 + 2 * jj + 1]);
#pragma unroll
        for (int n = 0; n < 4; n++) { ar[n * 4 + jj] = b_r; az[n * 4 + jj] = b_z; }
    }
#pragma unroll 2
    for (int k = 0; k < 128; k++) {
        float x0 = Xb[k], x1 = Xb[XP + k], x2 = Xb[2 * XP + k], x3 = Xb[3 * XP + k];
        ull xx[4] = { pk2(x0, x0), pk2(x1, x1), pk2(x2, x2), pk2(x3, x3) };
        ulonglong2 wra = *(const ulonglong2*)&Wr[k * 64 + j0];
        ulonglong2 wrb = *(const ulonglong2*)&Wr[k * 64 + j0 + 4];
        ulonglong2 wza = *(const ulonglong2*)&Wz[k * 64 + j0];
        ulonglong2 wzb = *(const ulonglong2*)&Wz[k * 64 + j0 + 4];
#pragma unroll
        for (int n = 0; n < 4; n++) {
            ar[n * 4 + 0] = f2fma(xx[n], wra.x, ar[n * 4 + 0]);
            ar[n * 4 + 1] = f2fma(xx[n], wra.y, ar[n * 4 + 1]);
            ar[n * 4 + 2] = f2fma(xx[n], wrb.x, ar[n * 4 + 2]);
            ar[n * 4 + 3] = f2fma(xx[n], wrb.y, ar[n * 4 + 3]);
            az[n * 4 + 0] = f2fma(xx[n], wza.x, az[n * 4 + 0]);
            az[n * 4 + 1] = f2fma(xx[n], wza.y, az[n * 4 + 1]);
            az[n * 4 + 2] = f2fma(xx[n], wzb.x, az[n * 4 + 2]);
            az[n * 4 + 3] = f2fma(xx[n], wzb.y, az[n * 4 + 3]);
        }
    }
    // ---- pass 2: i_n over H, h_n over h_prev ----
    ull ani[16], anh[16];
#pragma unroll
    for (int jj = 0; jj < 4; jj++) {
        ull b_i = pk2(bni[j0 + 2 * jj], bni[j0 + 2 * jj + 1]);
        ull b_h = pk2(bnh[j0 + 2 * jj], bnh[j0 + 2 * jj + 1]);
#pragma unroll
        for (int n = 0; n < 4; n++) { ani[n * 4 + jj] = b_i; anh[n * 4 + jj] = b_h; }
    }
#pragma unroll 2
    for (int k = 0; k < 64; k++) {
        float h0 = Xb[k], h1 = Xb[XP + k], h2 = Xb[2 * XP + k], h3 = Xb[3 * XP + k];
        float p0 = Xb[64 + k], p1 = Xb[XP + 64 + k], p2 = Xb[2 * XP + 64 + k], p3 = Xb[3 * XP + 64 + k];
        ull xh[4] = { pk2(h0, h0), pk2(h1, h1), pk2(h2, h2), pk2(h3, h3) };
        ull xp[4] = { pk2(p0, p0), pk2(p1, p1), pk2(p2, p2), pk2(p3, p3) };
        ulonglong2 wia = *(const ulonglong2*)&Wni[k * 64 + j0];
        ulonglong2 wib = *(const ulonglong2*)&Wni[k * 64 + j0 + 4];
        ulonglong2 wha = *(const ulonglong2*)&Wnh[k * 64 + j0];
        ulonglong2 whb = *(const ulonglong2*)&Wnh[k * 64 + j0 + 4];
#pragma unroll
        for (int n = 0; n < 4; n++) {
            ani[n * 4 + 0] = f2fma(xh[n], wia.x, ani[n * 4 + 0]);
            ani[n * 4 + 1] = f2fma(xh[n], wia.y, ani[n * 4 + 1]);
            ani[n * 4 + 2] = f2fma(xh[n], wib.x, ani[n * 4 + 2]);
            ani[n * 4 + 3] = f2fma(xh[n], wib.y, ani[n * 4 + 3]);
            anh[n * 4 + 0] = f2fma(xp[n], wha.x, anh[n * 4 + 0]);
            anh[n * 4 + 1] = f2fma(xp[n], wha.y, anh[n * 4 + 1]);
            anh[n * 4 + 2] = f2fma(xp[n], whb.x, anh[n * 4 + 2]);
            anh[n * 4 + 3] = f2fma(xp[n], whb.y, anh[n * 4 + 3]);
        }
    }

    // ---- combine + stores + fused pred (shfl reduce over the 8 jg lanes) ----
    float bo0 = __ldg(bout + 0), bo1 = __ldg(bout + 1), bo2 = __ldg(bout + 2);
#pragma unroll
    for (int n = 0; n < 4; n++) {
        int gn = nbase + ng * 4 + n;
        float res[8];
#pragma unroll
        for (int jj = 0; jj < 4; jj++) {
            float2 rr = up2(ar[n * 4 + jj]);
            float2 zz = up2(az[n * 4 + jj]);
            float2 vi = up2(ani[n * 4 + jj]);
            float2 vh = up2(anh[n * 4 + jj]);
#pragma unroll
            for (int s = 0; s < 2; s++) {
                float r = sigf(s ? rr.y : rr.x);
                float z = sigf(s ? zz.y : zz.x);
                float nn = tanhf((s ? vi.y : vi.x) + r * (s ? vh.y : vh.x));
                float hp = Xb[n * XP + 64 + j0 + jj * 2 + s];
                res[jj * 2 + s] = (1.f - z) * nn + z * hp;
            }
        }
        if (gn < Nn) {
            float4* o = (float4*)&out[(size_t)gn * 64 + j0];
            o[0] = make_float4(res[0], res[1], res[2], res[3]);
            o[1] = make_float4(res[4], res[5], res[6], res[7]);
        }
        // fused pred: partial dot over this thread's 8 j, reduce across jg lanes
        float p0 = 0.f, p1 = 0.f, p2 = 0.f;
#pragma unroll
        for (int s = 0; s < 8; s++) {
            float hv = res[s];
            int j = j0 + s;
            p0 += hv * wo[j * 3 + 0];
            p1 += hv * wo[j * 3 + 1];
            p2 += hv * wo[j * 3 + 2];
        }
#pragma unroll
        for (int m = 1; m < 8; m <<= 1) {
            p0 += __shfl_xor_sync(0xffffffffu, p0, m);
            p1 += __shfl_xor_sync(0xffffffffu, p1, m);
            p2 += __shfl_xor_sync(0xffffffffu, p2, m);
        }
        if (jg == 0 && gn < Nn) {
            float* pp = out + (size_t)Nn * 64 + (size_t)gn * 3;
            pp[0] = p0 + bo0; pp[1] = p1 + bo1; pp[2] = p2 + bo2;
        }
    }
}

// ---------------- launch ----------------
extern "C" void kernel_launch(void* const* d_in, const int* in_sizes, int n_in,
                              void* d_out, int out_size) {
    const float* x     = (const float*)d_in[0];
    const float* hprev = (const float*)d_in[1];
    const int*   en    = (const int*)d_in[2];
    const int*   eh    = (const int*)d_in[3];
    const int*   ea    = (const int*)d_in[4];
    const float* Wconv = (const float*)d_in[5];
    const float* bconv = (const float*)d_in[6];
    const float* Wmix  = (const float*)d_in[7];
    const float* bmix  = (const float*)d_in[8];
    const float* Wih   = (const float*)d_in[9];
    const float* Whh   = (const float*)d_in[10];
    const float* bih   = (const float*)d_in[11];
    const float* bhh   = (const float*)d_in[12];
    const float* Wout  = (const float*)d_in[13];
    const float* bout  = (const float*)d_in[14];
    float* out = (float*)d_out;

    (void)in_sizes; (void)n_in; (void)out_size;

    k_pre<<<10002, 256>>>(Wconv, bconv, Wmix, bmix, Wih, Whh, bih, bhh);
    k_scat1<<<31250, 256>>>(en, eh, ea, (const float4*)x);
    k_scat2<<<31250, 256>>>(en, eh, ea);

    const int smem = (128 * XP + 8192 * 2 + 4096 * 2 + 2048 + 64 * 5 + 192) * 4;
    cudaFuncSetAttribute(k_gru, cudaFuncAttributeMaxDynamicSharedMemorySize, smem);
    k_gru<<<782, 256, smem>>>(hprev, Wout, bout, out, NNODES);
}